// round 6
// baseline (speedup 1.0000x reference)
#include <cuda_runtime.h>
#include <cuda_fp16.h>
#include <cuda_bf16.h>

// Problem constants (fixed by the reference)
#define BB   2048
#define VV   2048
#define CC   512
#define MM   8
#define HH   16
#define EPSF 1e-6f
#define NBLK 148   // persistent: one block per SM

__device__ __forceinline__ float ex2_fast(float x) {
    float y;
    asm("ex2.approx.f32 %0, %1;" : "=f"(y) : "f"(x));
    return y;
}
__device__ __forceinline__ float rcp_fast(float x) {
    float y;
    asm("rcp.approx.f32 %0, %1;" : "=f"(y) : "f"(x));
    return y;
}
// Named *_fast to avoid colliding with cuda_fp16.hpp's h2tanh().
__device__ __forceinline__ __half2 h2tanh_fast(__half2 x) {
    unsigned xi = *reinterpret_cast<unsigned*>(&x), yi;
    asm("tanh.approx.f16x2 %0, %1;" : "=r"(yi) : "r"(xi));
    return *reinterpret_cast<__half2*>(&yi);
}

// Persistent kernel: 148 blocks, 512 threads (thread = channel c).
// The kernel is issue-slot-bound, so the MLP runs fully in packed f16x2:
// HFMA2 arg -> tanh.approx.f16x2 -> HFMA2 accumulate, with NO conversions in
// the inner loop. Four 4-term f16 accumulators bound the accumulation error;
// they are converted to f32 once per m-pair. Softmax stays f32.
__global__ __launch_bounds__(CC, 1) void gradoptim_attn_kernel(
    const float* __restrict__ preds,
    const int*   __restrict__ mask_ids,
    const float* __restrict__ W1,   // (C, 2, H)
    const float* __restrict__ b1,   // (C, H)
    const float* __restrict__ W2,   // (C, H)
    const float* __restrict__ b2,   // (C,)
    float*       __restrict__ out)  // (B, V)
{
    __shared__ float row[2][VV];

    const int c = threadIdx.x;

    // ---- Per-channel weights in f16x2 (both lanes equal), loaded once ----
    __half2 w1ah[HH], w1bh[HH], b1h[HH], w2h[HH];
    {
        const float4* W1p = reinterpret_cast<const float4*>(W1 + (size_t)c * 2 * HH);
        const float4* b1p = reinterpret_cast<const float4*>(b1 + (size_t)c * HH);
        const float4* W2p = reinterpret_cast<const float4*>(W2 + (size_t)c * HH);
        #pragma unroll
        for (int i = 0; i < 4; i++) {
            float4 a  = W1p[i];       // W1[c,0,4i..4i+3]
            float4 bq = W1p[4 + i];   // W1[c,1,4i..4i+3]
            float4 bv = b1p[i];
            float4 w2 = W2p[i];
            w1ah[4*i+0] = __float2half2_rn(a.x);  w1ah[4*i+1] = __float2half2_rn(a.y);
            w1ah[4*i+2] = __float2half2_rn(a.z);  w1ah[4*i+3] = __float2half2_rn(a.w);
            w1bh[4*i+0] = __float2half2_rn(bq.x); w1bh[4*i+1] = __float2half2_rn(bq.y);
            w1bh[4*i+2] = __float2half2_rn(bq.z); w1bh[4*i+3] = __float2half2_rn(bq.w);
            b1h[4*i+0]  = __float2half2_rn(bv.x); b1h[4*i+1]  = __float2half2_rn(bv.y);
            b1h[4*i+2]  = __float2half2_rn(bv.z); b1h[4*i+3]  = __float2half2_rn(bv.w);
            w2h[4*i+0]  = __float2half2_rn(w2.x); w2h[4*i+1]  = __float2half2_rn(w2.y);
            w2h[4*i+2]  = __float2half2_rn(w2.z); w2h[4*i+3]  = __float2half2_rn(w2.w);
        }
    }
    const float b2c = b2[c];

    int idx[MM];
    {
        const int4* mi = reinterpret_cast<const int4*>(mask_ids + (size_t)c * MM);
        int4 i0 = mi[0], i1 = mi[1];
        idx[0] = i0.x; idx[1] = i0.y; idx[2] = i0.z; idx[3] = i0.w;
        idx[4] = i1.x; idx[5] = i1.y; idx[6] = i1.z; idx[7] = i1.w;
    }

    const float LOG2E = 1.4426950408889634f;

    int b = blockIdx.x;
    int buf = 0;
    float4 v4;
    if (b < BB) v4 = reinterpret_cast<const float4*>(preds + (size_t)b * VV)[c];

    while (b < BB) {
        // Stage current row into smem; copy untouched tail columns verbatim.
        reinterpret_cast<float4*>(row[buf])[c] = v4;
        if (c >= CC / 4)
            reinterpret_cast<float4*>(out + (size_t)b * VV)[c] = v4;
        __syncthreads();

        // Prefetch next row so LDG latency hides under compute.
        const int bn = b + NBLK;
        if (bn < BB) v4 = reinterpret_cast<const float4*>(preds + (size_t)bn * VV)[c];

        // ---- Compute ----
        const float h_a = row[buf][c];
        float hm[MM];
        #pragma unroll
        for (int m = 0; m < MM; m++) hm[m] = row[buf][idx[m]];

        // u[h] = h_a*W1[c,0,h] + b1[c,h] entirely in f16x2.
        const __half2 ha2 = __float2half2_rn(h_a);
        __half2 uh[HH];
        #pragma unroll
        for (int h = 0; h < HH; h++)
            uh[h] = __hfma2(ha2, w1ah[h], b1h[h]);

        // Scores: two m-values per half2 lane. Fully-f16 inner loop; four
        // 4-term accumulators, converted to f32 once per pair.
        float sc[MM];
        #pragma unroll
        for (int p = 0; p < MM / 2; p++) {
            __half2 x2 = __floats2half2_rn(hm[2*p], hm[2*p + 1]);
            __half2 a0 = __float2half2_rn(0.0f);
            __half2 a1 = a0, a2 = a0, a3 = a0;
            #pragma unroll
            for (int h = 0; h < HH; h += 4) {
                a0 = __hfma2(w2h[h+0], h2tanh_fast(__hfma2(x2, w1bh[h+0], uh[h+0])), a0);
                a1 = __hfma2(w2h[h+1], h2tanh_fast(__hfma2(x2, w1bh[h+1], uh[h+1])), a1);
                a2 = __hfma2(w2h[h+2], h2tanh_fast(__hfma2(x2, w1bh[h+2], uh[h+2])), a2);
                a3 = __hfma2(w2h[h+3], h2tanh_fast(__hfma2(x2, w1bh[h+3], uh[h+3])), a3);
            }
            float2 f0 = __half22float2(a0);
            float2 f1 = __half22float2(a1);
            float2 f2 = __half22float2(a2);
            float2 f3 = __half22float2(a3);
            sc[2*p]     = ((f0.x + f1.x) + (f2.x + f3.x)) + b2c;
            sc[2*p + 1] = ((f0.y + f1.y) + (f2.y + f3.y)) + b2c;
        }

        // Softmax over m; weighted sum of h_m in full f32.
        float mx = sc[0];
        #pragma unroll
        for (int m = 1; m < MM; m++) mx = fmaxf(mx, sc[m]);

        float sum = 0.0f, ws = 0.0f;
        #pragma unroll
        for (int m = 0; m < MM; m++) {
            float e = ex2_fast((sc[m] - mx) * LOG2E);
            sum = sum + e;
            ws  = fmaf(e, hm[m], ws);
        }
        const float weighted  = ws * rcp_fast(sum);
        const float corrected = fmaxf(h_a, weighted + EPSF);

        out[(size_t)b * VV + c] = corrected;

        buf ^= 1;
        b = bn;
    }
}

extern "C" void kernel_launch(void* const* d_in, const int* in_sizes, int n_in,
                              void* d_out, int out_size) {
    (void)in_sizes; (void)n_in; (void)out_size;
    const float* preds    = (const float*)d_in[0];
    // d_in[1] = ground_truth (unused by the reference)
    const int*   mask_ids = (const int*)  d_in[2];
    const float* W1       = (const float*)d_in[3];
    const float* b1       = (const float*)d_in[4];
    const float* W2       = (const float*)d_in[5];
    const float* b2       = (const float*)d_in[6];
    float*       out      = (float*)d_out;

    gradoptim_attn_kernel<<<NBLK, CC>>>(preds, mask_ids, W1, b1, W2, b2, out);
}

// round 8
// speedup vs baseline: 1.0429x; 1.0429x over previous
#include <cuda_runtime.h>
#include <cuda_fp16.h>
#include <cuda_bf16.h>
#include <cstdint>

// Problem constants (fixed by the reference)
#define BB    2048
#define VV    2048
#define CC    512
#define MM    8
#define HH    16
#define EPSF  1e-6f
#define NBLK  148          // persistent: one block per SM
#define PAIRS (BB / 2)     // 1024 row-pairs

__device__ __forceinline__ float ex2_fast(float x) {
    float y;
    asm("ex2.approx.f32 %0, %1;" : "=f"(y) : "f"(x));
    return y;
}
__device__ __forceinline__ float rcp_fast(float x) {
    float y;
    asm("rcp.approx.f32 %0, %1;" : "=f"(y) : "f"(x));
    return y;
}
// Named *_fast to avoid colliding with cuda_fp16.hpp's h2tanh().
__device__ __forceinline__ __half2 h2tanh_fast(__half2 x) {
    unsigned xi = *reinterpret_cast<unsigned*>(&x), yi;
    asm("tanh.approx.f16x2 %0, %1;" : "=r"(yi) : "r"(xi));
    return *reinterpret_cast<__half2*>(&yi);
}
__device__ __forceinline__ void cpasync16(void* smem_ptr, const float* g) {
    unsigned int saddr = (unsigned int)__cvta_generic_to_shared(smem_ptr);
    asm volatile("cp.async.cg.shared.global [%0], [%1], 16;" :: "r"(saddr), "l"(g));
}
#define CP_COMMIT() asm volatile("cp.async.commit_group;" ::: "memory")
#define CP_WAIT0()  asm volatile("cp.async.wait_group 0;" ::: "memory")

// Persistent kernel: 148 blocks, 512 threads (thread = channel c).
// TWO rows per iteration, packed into the two f16x2 lanes (lane = row).
// Halves the iteration/barrier count and doubles ILP against the latency
// floor that Rounds 5-6 showed to be binding. Rows staged via cp.async into
// a 2-pair smem ring; tail columns copied smem->gmem after the barrier.
__global__ __launch_bounds__(CC, 1) void gradoptim_attn_kernel(
    const float* __restrict__ preds,
    const int*   __restrict__ mask_ids,
    const float* __restrict__ W1,   // (C, 2, H)
    const float* __restrict__ b1,   // (C, H)
    const float* __restrict__ W2,   // (C, H)
    const float* __restrict__ b2,   // (C,)
    float*       __restrict__ out)  // (B, V)
{
    __shared__ float rows[2][2][VV];   // [ring buf][row in pair][col]

    const int c = threadIdx.x;

    // ---- Per-channel weights in f16x2 (both lanes equal), loaded once ----
    __half2 w1ah[HH], w1bh[HH], b1h[HH], w2h[HH];
    {
        const float4* W1p = reinterpret_cast<const float4*>(W1 + (size_t)c * 2 * HH);
        const float4* b1p = reinterpret_cast<const float4*>(b1 + (size_t)c * HH);
        const float4* W2p = reinterpret_cast<const float4*>(W2 + (size_t)c * HH);
        #pragma unroll
        for (int i = 0; i < 4; i++) {
            float4 a  = W1p[i];       // W1[c,0,4i..4i+3]
            float4 bq = W1p[4 + i];   // W1[c,1,4i..4i+3]
            float4 bv = b1p[i];
            float4 w2 = W2p[i];
            w1ah[4*i+0] = __float2half2_rn(a.x);  w1ah[4*i+1] = __float2half2_rn(a.y);
            w1ah[4*i+2] = __float2half2_rn(a.z);  w1ah[4*i+3] = __float2half2_rn(a.w);
            w1bh[4*i+0] = __float2half2_rn(bq.x); w1bh[4*i+1] = __float2half2_rn(bq.y);
            w1bh[4*i+2] = __float2half2_rn(bq.z); w1bh[4*i+3] = __float2half2_rn(bq.w);
            b1h[4*i+0]  = __float2half2_rn(bv.x); b1h[4*i+1]  = __float2half2_rn(bv.y);
            b1h[4*i+2]  = __float2half2_rn(bv.z); b1h[4*i+3]  = __float2half2_rn(bv.w);
            w2h[4*i+0]  = __float2half2_rn(w2.x); w2h[4*i+1]  = __float2half2_rn(w2.y);
            w2h[4*i+2]  = __float2half2_rn(w2.z); w2h[4*i+3]  = __float2half2_rn(w2.w);
        }
    }
    const float b2c = b2[c];

    int idx[MM];
    {
        const int4* mi = reinterpret_cast<const int4*>(mask_ids + (size_t)c * MM);
        int4 i0 = mi[0], i1 = mi[1];
        idx[0] = i0.x; idx[1] = i0.y; idx[2] = i0.z; idx[3] = i0.w;
        idx[4] = i1.x; idx[5] = i1.y; idx[6] = i1.z; idx[7] = i1.w;
    }

    const float LOG2E = 1.4426950408889634f;

    // ---- Prologue: stage first pair into ring buf 0 ----
    int p = blockIdx.x;
    if (p < PAIRS) {
        cpasync16(&rows[0][0][c * 4], preds + (size_t)(2 * p)     * VV + c * 4);
        cpasync16(&rows[0][1][c * 4], preds + (size_t)(2 * p + 1) * VV + c * 4);
        CP_COMMIT();
    }

    int buf = 0;
    while (p < PAIRS) {
        CP_WAIT0();          // my copies for pair p complete
        __syncthreads();     // everyone's copies complete; prev pair's reads done

        // Prefetch next pair into the other ring slot (overlaps compute).
        const int pn = p + NBLK;
        if (pn < PAIRS) {
            cpasync16(&rows[buf ^ 1][0][c * 4], preds + (size_t)(2 * pn)     * VV + c * 4);
            cpasync16(&rows[buf ^ 1][1][c * 4], preds + (size_t)(2 * pn + 1) * VV + c * 4);
            CP_COMMIT();
        }

        const int r0 = 2 * p, r1 = 2 * p + 1;

        // Copy untouched tail columns [512,2048) straight from smem.
        if (c >= CC / 4) {
            float4 t0 = reinterpret_cast<float4*>(rows[buf][0])[c];
            float4 t1 = reinterpret_cast<float4*>(rows[buf][1])[c];
            reinterpret_cast<float4*>(out + (size_t)r0 * VV)[c] = t0;
            reinterpret_cast<float4*>(out + (size_t)r1 * VV)[c] = t1;
        }

        // ---- Compute both rows; half2 lanes = (row0, row1) ----
        const float ha0 = rows[buf][0][c];
        const float ha1 = rows[buf][1][c];
        float hm0[MM], hm1[MM];
        #pragma unroll
        for (int m = 0; m < MM; m++) {
            hm0[m] = rows[buf][0][idx[m]];
            hm1[m] = rows[buf][1][idx[m]];
        }

        const __half2 ha2 = __floats2half2_rn(ha0, ha1);
        __half2 uh[HH];
        #pragma unroll
        for (int h = 0; h < HH; h++)
            uh[h] = __hfma2(ha2, w1ah[h], b1h[h]);

        float sc0[MM], sc1[MM];
        #pragma unroll
        for (int m = 0; m < MM; m++) {
            __half2 x2 = __floats2half2_rn(hm0[m], hm1[m]);
            __half2 aE = __float2half2_rn(0.0f);
            __half2 aO = aE;
            #pragma unroll
            for (int h = 0; h < HH; h += 2) {
                aE = __hfma2(w2h[h],     h2tanh_fast(__hfma2(x2, w1bh[h],     uh[h])),     aE);
                aO = __hfma2(w2h[h + 1], h2tanh_fast(__hfma2(x2, w1bh[h + 1], uh[h + 1])), aO);
            }
            float2 fE = __half22float2(aE);
            float2 fO = __half22float2(aO);
            sc0[m] = (fE.x + fO.x) + b2c;
            sc1[m] = (fE.y + fO.y) + b2c;
        }

        // Softmax + weighted sum per row, f32. Independent chains -> ILP.
        float mx0 = sc0[0], mx1 = sc1[0];
        #pragma unroll
        for (int m = 1; m < MM; m++) {
            mx0 = fmaxf(mx0, sc0[m]);
            mx1 = fmaxf(mx1, sc1[m]);
        }
        float su0 = 0.0f, ws0 = 0.0f, su1 = 0.0f, ws1 = 0.0f;
        #pragma unroll
        for (int m = 0; m < MM; m++) {
            float e0 = ex2_fast((sc0[m] - mx0) * LOG2E);
            float e1 = ex2_fast((sc1[m] - mx1) * LOG2E);
            su0 += e0;  ws0 = fmaf(e0, hm0[m], ws0);
            su1 += e1;  ws1 = fmaf(e1, hm1[m], ws1);
        }
        const float cor0 = fmaxf(ha0, ws0 * rcp_fast(su0) + EPSF);
        const float cor1 = fmaxf(ha1, ws1 * rcp_fast(su1) + EPSF);

        out[(size_t)r0 * VV + c] = cor0;
        out[(size_t)r1 * VV + c] = cor1;

        buf ^= 1;
        p = pn;
    }
}

extern "C" void kernel_launch(void* const* d_in, const int* in_sizes, int n_in,
                              void* d_out, int out_size) {
    (void)in_sizes; (void)n_in; (void)out_size;
    const float* preds    = (const float*)d_in[0];
    // d_in[1] = ground_truth (unused by the reference)
    const int*   mask_ids = (const int*)  d_in[2];
    const float* W1       = (const float*)d_in[3];
    const float* b1       = (const float*)d_in[4];
    const float* W2       = (const float*)d_in[5];
    const float* b2       = (const float*)d_in[6];
    float*       out      = (float*)d_out;

    gradoptim_attn_kernel<<<NBLK, CC>>>(preds, mask_ids, W1, b1, W2, b2, out);
}